// round 1
// baseline (speedup 1.0000x reference)
#include <cuda_runtime.h>
#include <cstdint>

// Problem constants (match reference)
constexpr int N_NODES = 50000;
constexpr int N_EDGES = 800000;
constexpr int D       = 256;     // D_IN == D_OUT
constexpr float BN_EPS = 1e-5f;

// -------- device scratch (no allocations allowed) --------
__device__ float g_h[(size_t)N_NODES * D];   // 51.2 MB: h = x @ W^T
__device__ float g_deg[N_NODES];
__device__ float g_dinv[N_NODES];
__device__ float g_sum[D];
__device__ float g_sumsq[D];
__device__ int   g_is64;

// -------- helpers --------
__device__ __forceinline__ int edge_idx(const void* e, long long pos, int is64) {
    if (is64) return (int)((const long long*)e)[pos];
    return ((const int*)e)[pos];
}

// -------- 0: detect edge_index element width --------
// int64 little-endian values < 50000 -> every odd 32-bit word is 0.
// int32 random indices -> odd words are ~never all zero (p ~ (1/50000)^64).
__global__ void detect_kernel(const unsigned int* e) {
    int lane = threadIdx.x;                       // 32 threads
    unsigned v = e[2 * lane + 1] | e[2 * (lane + 32) + 1];
    unsigned any = __ballot_sync(0xffffffffu, v != 0u);
    if (lane == 0) g_is64 = (any == 0u) ? 1 : 0;
}

// -------- 1: zero accumulators --------
__global__ void zero_kernel() {
    int i = blockIdx.x * blockDim.x + threadIdx.x;
    if (i < N_NODES) g_deg[i] = 0.0f;
    if (i < D) { g_sum[i] = 0.0f; g_sumsq[i] = 0.0f; }
}

// -------- 2: degree (over col, self-loop added later as +1) --------
__global__ void deg_kernel(const void* eidx) {
    int e = blockIdx.x * blockDim.x + threadIdx.x;
    if (e >= N_EDGES) return;
    int is64 = g_is64;
    int c = edge_idx(eidx, (long long)N_EDGES + e, is64);
    atomicAdd(&g_deg[c], 1.0f);
}

// -------- 3: dinv = rsqrt(deg + 1) (self loop makes deg >= 1) --------
__global__ void dinv_kernel() {
    int i = blockIdx.x * blockDim.x + threadIdx.x;
    if (i >= N_NODES) return;
    g_dinv[i] = rsqrtf(g_deg[i] + 1.0f);
}

// -------- 4: SGEMM  h[m][n] = sum_k X[m][k] * W[n][k]  (M=50000, N=K=256) --
__global__ void __launch_bounds__(256) gemm_kernel(const float* __restrict__ X,
                                                   const float* __restrict__ W) {
    __shared__ float As[8][128];
    __shared__ float Bs[8][128];
    const int bx = blockIdx.x;        // n-tile: 0..1
    const int by = blockIdx.y;        // m-tile: 0..390
    const int tid = threadIdx.x;
    const int tx = tid & 15;          // 0..15
    const int ty = tid >> 4;          // 0..15
    const int m0 = by * 128;
    const int n0 = bx * 128;

    const int l_row = tid >> 1;           // 0..127
    const int l_k   = (tid & 1) * 4;      // 0 or 4

    float acc[8][8];
#pragma unroll
    for (int i = 0; i < 8; i++)
#pragma unroll
        for (int j = 0; j < 8; j++) acc[i][j] = 0.0f;

    for (int k0 = 0; k0 < 256; k0 += 8) {
        // load A tile (transposed into As[k][m])
        float4 a4 = make_float4(0.f, 0.f, 0.f, 0.f);
        int gm = m0 + l_row;
        if (gm < N_NODES)
            a4 = *(const float4*)(X + (size_t)gm * D + k0 + l_k);
        As[l_k + 0][l_row] = a4.x;
        As[l_k + 1][l_row] = a4.y;
        As[l_k + 2][l_row] = a4.z;
        As[l_k + 3][l_row] = a4.w;
        // load B tile: Bs[k][n] = W[n0+n][k0+k]
        float4 b4 = *(const float4*)(W + (size_t)(n0 + l_row) * D + k0 + l_k);
        Bs[l_k + 0][l_row] = b4.x;
        Bs[l_k + 1][l_row] = b4.y;
        Bs[l_k + 2][l_row] = b4.z;
        Bs[l_k + 3][l_row] = b4.w;
        __syncthreads();

#pragma unroll
        for (int k = 0; k < 8; ++k) {
            float rm[8], rn[8];
#pragma unroll
            for (int i = 0; i < 4; i++) {
                rm[i]     = As[k][ty * 4 + i];
                rm[i + 4] = As[k][64 + ty * 4 + i];
            }
#pragma unroll
            for (int j = 0; j < 4; j++) {
                rn[j]     = Bs[k][tx * 4 + j];
                rn[j + 4] = Bs[k][64 + tx * 4 + j];
            }
#pragma unroll
            for (int i = 0; i < 8; i++)
#pragma unroll
                for (int j = 0; j < 8; j++) acc[i][j] += rm[i] * rn[j];
        }
        __syncthreads();
    }

#pragma unroll
    for (int i = 0; i < 8; i++) {
        int gm = m0 + ((i < 4) ? (ty * 4 + i) : (64 + ty * 4 + (i - 4)));
        if (gm >= N_NODES) continue;
        float* hr = g_h + (size_t)gm * D;
        *(float4*)(hr + n0 + tx * 4)      = make_float4(acc[i][0], acc[i][1], acc[i][2], acc[i][3]);
        *(float4*)(hr + n0 + 64 + tx * 4) = make_float4(acc[i][4], acc[i][5], acc[i][6], acc[i][7]);
    }
}

// -------- 5: init agg = h * dinv^2 (self-loop message) + bias --> d_out ----
__global__ void init_kernel(const float* __restrict__ bias, float* __restrict__ out) {
    int idx = blockIdx.x * blockDim.x + threadIdx.x;   // over N_NODES*64 float4s
    if (idx >= N_NODES * (D / 4)) return;
    int node = idx >> 6;
    int j4 = idx & 63;
    float s = g_dinv[node];
    s = s * s;
    float4 h4 = ((const float4*)g_h)[idx];
    float4 b4 = ((const float4*)bias)[j4];
    float4 v;
    v.x = h4.x * s + b4.x;
    v.y = h4.y * s + b4.y;
    v.z = h4.z * s + b4.z;
    v.w = h4.w * s + b4.w;
    ((float4*)out)[idx] = v;
}

// -------- 6: edge scatter: out[col] += h[row] * (dinv[row]*dinv[col]) ------
__global__ void __launch_bounds__(256) scatter_kernel(const void* __restrict__ eidx,
                                                      float* __restrict__ out) {
    int warp = (blockIdx.x * blockDim.x + threadIdx.x) >> 5;
    int lane = threadIdx.x & 31;
    if (warp >= N_EDGES) return;
    int is64 = g_is64;
    int r = edge_idx(eidx, warp, is64);
    int c = edge_idx(eidx, (long long)N_EDGES + warp, is64);
    float nrm = g_dinv[r] * g_dinv[c];
    const float4* hr = (const float4*)(g_h + (size_t)r * D);
    float4* oc = (float4*)(out + (size_t)c * D);
#pragma unroll
    for (int i = lane; i < D / 4; i += 32) {
        float4 v = hr[i];
        v.x *= nrm; v.y *= nrm; v.z *= nrm; v.w *= nrm;
        asm volatile("red.global.add.v4.f32 [%0], {%1,%2,%3,%4};"
                     :: "l"(oc + i), "f"(v.x), "f"(v.y), "f"(v.z), "f"(v.w)
                     : "memory");
    }
}

// -------- 7: per-feature sum / sumsq (column reduction) --------------------
__global__ void __launch_bounds__(256) stats_kernel(const float* __restrict__ out) {
    const int d = threadIdx.x;            // one thread per feature column
    const int r0 = blockIdx.x * 256;
    const int r1 = min(r0 + 256, N_NODES);
    float s = 0.0f, sq = 0.0f;
    for (int r = r0; r < r1; ++r) {
        float v = out[(size_t)r * D + d];
        s += v;
        sq += v * v;
    }
    atomicAdd(&g_sum[d], s);
    atomicAdd(&g_sumsq[d], sq);
}

// -------- 8: BatchNorm + ReLU in place on d_out ----------------------------
__global__ void finalize_kernel(const float* __restrict__ gamma,
                                const float* __restrict__ beta,
                                float* __restrict__ out) {
    int idx = blockIdx.x * blockDim.x + threadIdx.x;   // over N_NODES*64 float4s
    if (idx >= N_NODES * (D / 4)) return;
    int j4 = idx & 63;
    const float invN = 1.0f / (float)N_NODES;
    float4 s4  = ((const float4*)g_sum)[j4];
    float4 q4  = ((const float4*)g_sumsq)[j4];
    float4 g4  = ((const float4*)gamma)[j4];
    float4 b4  = ((const float4*)beta)[j4];
    float4 v = ((const float4*)out)[idx];

    float m, var, k;
    float4 y;
    m = s4.x * invN; var = q4.x * invN - m * m; k = g4.x * rsqrtf(var + BN_EPS);
    y.x = fmaxf((v.x - m) * k + b4.x, 0.0f);
    m = s4.y * invN; var = q4.y * invN - m * m; k = g4.y * rsqrtf(var + BN_EPS);
    y.y = fmaxf((v.y - m) * k + b4.y, 0.0f);
    m = s4.z * invN; var = q4.z * invN - m * m; k = g4.z * rsqrtf(var + BN_EPS);
    y.z = fmaxf((v.z - m) * k + b4.z, 0.0f);
    m = s4.w * invN; var = q4.w * invN - m * m; k = g4.w * rsqrtf(var + BN_EPS);
    y.w = fmaxf((v.w - m) * k + b4.w, 0.0f);
    ((float4*)out)[idx] = y;
}

// ---------------------------------------------------------------------------
extern "C" void kernel_launch(void* const* d_in, const int* in_sizes, int n_in,
                              void* d_out, int out_size) {
    const float* x     = (const float*)d_in[0];
    const void*  eidx  = d_in[1];               // int64 or int32, detected on device
    const float* W     = (const float*)d_in[2];
    const float* bias  = (const float*)d_in[3];
    const float* gamma = (const float*)d_in[4];
    const float* beta  = (const float*)d_in[5];
    float* out = (float*)d_out;

    detect_kernel<<<1, 32>>>((const unsigned int*)eidx);
    zero_kernel<<<(N_NODES + 255) / 256, 256>>>();
    deg_kernel<<<(N_EDGES + 255) / 256, 256>>>(eidx);
    dinv_kernel<<<(N_NODES + 255) / 256, 256>>>();

    dim3 ggrid(2, (N_NODES + 127) / 128);
    gemm_kernel<<<ggrid, 256>>>(x, W);

    int nvec = N_NODES * (D / 4);
    init_kernel<<<(nvec + 255) / 256, 256>>>(bias, out);

    // one warp per edge: 8 warps/block -> 100000 blocks
    scatter_kernel<<<(N_EDGES + 7) / 8, 256>>>(eidx, out);

    stats_kernel<<<(N_NODES + 255) / 256, 256>>>(out);
    finalize_kernel<<<(nvec + 255) / 256, 256>>>(gamma, beta, out);
}

// round 2
// speedup vs baseline: 1.4755x; 1.4755x over previous
#include <cuda_runtime.h>
#include <cstdint>

// Problem constants (match reference)
constexpr int N_NODES = 50000;
constexpr int N_EDGES = 800000;
constexpr int D       = 256;     // D_IN == D_OUT
constexpr float BN_EPS = 1e-5f;

// -------- device scratch (no allocations allowed) --------
__device__ float g_h[(size_t)N_NODES * D];   // 51.2 MB: h = x @ W^T
__device__ float g_deg[N_NODES];
__device__ float g_dinv[N_NODES];
__device__ float g_sum[D];
__device__ float g_sumsq[D];
__device__ int   g_is64;

// -------- helpers --------
__device__ __forceinline__ int edge_idx(const void* e, long long pos, int is64) {
    if (is64) return (int)((const long long*)e)[pos];
    return ((const int*)e)[pos];
}

__device__ __forceinline__ uint32_t f2tf32(float x) {
    uint32_t r;
    asm("cvt.rna.tf32.f32 %0, %1;" : "=r"(r) : "f"(x));
    return r;
}

// -------- 0: detect edge_index element width --------
__global__ void detect_kernel(const unsigned int* e) {
    int lane = threadIdx.x;                       // 32 threads
    unsigned v = e[2 * lane + 1] | e[2 * (lane + 32) + 1];
    unsigned any = __ballot_sync(0xffffffffu, v != 0u);
    if (lane == 0) g_is64 = (any == 0u) ? 1 : 0;
}

// -------- 1: zero accumulators --------
__global__ void zero_kernel() {
    int i = blockIdx.x * blockDim.x + threadIdx.x;
    if (i < N_NODES) g_deg[i] = 0.0f;
    if (i < D) { g_sum[i] = 0.0f; g_sumsq[i] = 0.0f; }
}

// -------- 2: degree over col --------
__global__ void deg_kernel(const void* eidx) {
    int e = blockIdx.x * blockDim.x + threadIdx.x;
    if (e >= N_EDGES) return;
    int is64 = g_is64;
    int c = edge_idx(eidx, (long long)N_EDGES + e, is64);
    atomicAdd(&g_deg[c], 1.0f);
}

// -------- 3: dinv = rsqrt(deg + 1) --------
__global__ void dinv_kernel() {
    int i = blockIdx.x * blockDim.x + threadIdx.x;
    if (i >= N_NODES) return;
    g_dinv[i] = rsqrtf(g_deg[i] + 1.0f);
}

// -------- 4: tf32 tensor-core GEMM, fused self-loop+bias epilogue ----------
// h[m][n] = sum_k X[m][k] * W[n][k]; writes g_h and out = h*dinv^2 + bias.
// BM=128, BN=128, BK=32; 8 warps as 2(M) x 4(N); warp tile 64x32.
constexpr int BK = 32;
constexpr int KS = BK + 4;   // smem k-stride: 36 words (36 % 32 == 4 -> conflict-free)

__global__ void __launch_bounds__(256, 2) gemm_tf32_kernel(const float* __restrict__ X,
                                                           const float* __restrict__ W,
                                                           const float* __restrict__ bias,
                                                           float* __restrict__ out) {
    __shared__ uint32_t As[128][KS];
    __shared__ uint32_t Bs[128][KS];

    const int tid  = threadIdx.x;
    const int lane = tid & 31;
    const int wid  = tid >> 5;
    const int grp  = lane >> 2;       // 0..7
    const int tq   = lane & 3;        // 0..3
    const int warp_m = wid & 1;       // 0..1
    const int warp_n = wid >> 1;      // 0..3
    const int wm0 = warp_m * 64;
    const int wn0 = warp_n * 32;
    const int m0 = blockIdx.y * 128;
    const int n0 = blockIdx.x * 128;

    const int ldrow = tid >> 3;       // 0..31
    const int ldk   = (tid & 7) * 4;  // 0,4,...,28

    float acc[4][4][4];
#pragma unroll
    for (int mi = 0; mi < 4; ++mi)
#pragma unroll
        for (int ni = 0; ni < 4; ++ni)
#pragma unroll
            for (int j = 0; j < 4; ++j) acc[mi][ni][j] = 0.0f;

    for (int k0 = 0; k0 < 256; k0 += BK) {
#pragma unroll
        for (int it = 0; it < 4; ++it) {
            int row = ldrow + it * 32;
            // A tile (guard tail rows)
            int gm = m0 + row;
            float4 a = make_float4(0.f, 0.f, 0.f, 0.f);
            if (gm < N_NODES)
                a = *(const float4*)(X + (size_t)gm * D + k0 + ldk);
            uint4 at;
            at.x = f2tf32(a.x); at.y = f2tf32(a.y);
            at.z = f2tf32(a.z); at.w = f2tf32(a.w);
            *(uint4*)(&As[row][ldk]) = at;
            // B tile (W rows always valid: 256 rows total)
            int gn = n0 + row;
            float4 b = *(const float4*)(W + (size_t)gn * D + k0 + ldk);
            uint4 bt;
            bt.x = f2tf32(b.x); bt.y = f2tf32(b.y);
            bt.z = f2tf32(b.z); bt.w = f2tf32(b.w);
            *(uint4*)(&Bs[row][ldk]) = bt;
        }
        __syncthreads();

#pragma unroll
        for (int kk = 0; kk < 4; ++kk) {
            const int kb = kk * 8;
            uint32_t aR[4][4];
#pragma unroll
            for (int mi = 0; mi < 4; ++mi) {
                int mb = wm0 + mi * 16;
                aR[mi][0] = As[mb + grp][kb + tq];
                aR[mi][1] = As[mb + grp + 8][kb + tq];
                aR[mi][2] = As[mb + grp][kb + tq + 4];
                aR[mi][3] = As[mb + grp + 8][kb + tq + 4];
            }
            uint32_t bR[4][2];
#pragma unroll
            for (int ni = 0; ni < 4; ++ni) {
                int nb = wn0 + ni * 8;
                bR[ni][0] = Bs[nb + grp][kb + tq];
                bR[ni][1] = Bs[nb + grp][kb + tq + 4];
            }
#pragma unroll
            for (int mi = 0; mi < 4; ++mi)
#pragma unroll
                for (int ni = 0; ni < 4; ++ni) {
                    asm volatile(
                        "mma.sync.aligned.m16n8k8.row.col.f32.tf32.tf32.f32 "
                        "{%0,%1,%2,%3}, {%4,%5,%6,%7}, {%8,%9}, {%0,%1,%2,%3};\n"
                        : "+f"(acc[mi][ni][0]), "+f"(acc[mi][ni][1]),
                          "+f"(acc[mi][ni][2]), "+f"(acc[mi][ni][3])
                        : "r"(aR[mi][0]), "r"(aR[mi][1]), "r"(aR[mi][2]), "r"(aR[mi][3]),
                          "r"(bR[ni][0]), "r"(bR[ni][1]));
                }
        }
        __syncthreads();
    }

    // epilogue: write h and out = h*dinv^2 + bias
#pragma unroll
    for (int mi = 0; mi < 4; ++mi) {
#pragma unroll
        for (int half = 0; half < 2; ++half) {
            int r = m0 + wm0 + mi * 16 + grp + half * 8;
            if (r >= N_NODES) continue;
            float dv = g_dinv[r];
            float s = dv * dv;
            float* hrow = g_h + (size_t)r * D;
            float* orow = out + (size_t)r * D;
#pragma unroll
            for (int ni = 0; ni < 4; ++ni) {
                int c = n0 + wn0 + ni * 8 + tq * 2;
                float v0 = acc[mi][ni][half * 2 + 0];
                float v1 = acc[mi][ni][half * 2 + 1];
                *(float2*)(hrow + c) = make_float2(v0, v1);
                float2 bb = *(const float2*)(bias + c);
                *(float2*)(orow + c) = make_float2(fmaf(v0, s, bb.x), fmaf(v1, s, bb.y));
            }
        }
    }
}

// -------- 6: edge scatter: out[col] += h[row] * (dinv[row]*dinv[col]) ------
__global__ void __launch_bounds__(256) scatter_kernel(const void* __restrict__ eidx,
                                                      float* __restrict__ out) {
    int warp = (blockIdx.x * blockDim.x + threadIdx.x) >> 5;
    int lane = threadIdx.x & 31;
    if (warp >= N_EDGES) return;
    int is64 = g_is64;
    int r = edge_idx(eidx, warp, is64);
    int c = edge_idx(eidx, (long long)N_EDGES + warp, is64);
    float nrm = g_dinv[r] * g_dinv[c];
    const float4* hr = (const float4*)(g_h + (size_t)r * D);
    float4* oc = (float4*)(out + (size_t)c * D);
#pragma unroll
    for (int i = lane; i < D / 4; i += 32) {
        float4 v = hr[i];
        v.x *= nrm; v.y *= nrm; v.z *= nrm; v.w *= nrm;
        asm volatile("red.global.add.v4.f32 [%0], {%1,%2,%3,%4};"
                     :: "l"(oc + i), "f"(v.x), "f"(v.y), "f"(v.z), "f"(v.w)
                     : "memory");
    }
}

// -------- 7: per-feature sum / sumsq --------
__global__ void __launch_bounds__(256) stats_kernel(const float* __restrict__ out) {
    const int d = threadIdx.x;
    const int r0 = blockIdx.x * 256;
    const int r1 = min(r0 + 256, N_NODES);
    float s = 0.0f, sq = 0.0f;
    for (int r = r0; r < r1; ++r) {
        float v = out[(size_t)r * D + d];
        s += v;
        sq += v * v;
    }
    atomicAdd(&g_sum[d], s);
    atomicAdd(&g_sumsq[d], sq);
}

// -------- 8: BatchNorm + ReLU in place --------
__global__ void finalize_kernel(const float* __restrict__ gamma,
                                const float* __restrict__ beta,
                                float* __restrict__ out) {
    int idx = blockIdx.x * blockDim.x + threadIdx.x;
    if (idx >= N_NODES * (D / 4)) return;
    int j4 = idx & 63;
    const float invN = 1.0f / (float)N_NODES;
    float4 s4  = ((const float4*)g_sum)[j4];
    float4 q4  = ((const float4*)g_sumsq)[j4];
    float4 g4  = ((const float4*)gamma)[j4];
    float4 b4  = ((const float4*)beta)[j4];
    float4 v = ((const float4*)out)[idx];

    float m, var, k;
    float4 y;
    m = s4.x * invN; var = q4.x * invN - m * m; k = g4.x * rsqrtf(var + BN_EPS);
    y.x = fmaxf((v.x - m) * k + b4.x, 0.0f);
    m = s4.y * invN; var = q4.y * invN - m * m; k = g4.y * rsqrtf(var + BN_EPS);
    y.y = fmaxf((v.y - m) * k + b4.y, 0.0f);
    m = s4.z * invN; var = q4.z * invN - m * m; k = g4.z * rsqrtf(var + BN_EPS);
    y.z = fmaxf((v.z - m) * k + b4.z, 0.0f);
    m = s4.w * invN; var = q4.w * invN - m * m; k = g4.w * rsqrtf(var + BN_EPS);
    y.w = fmaxf((v.w - m) * k + b4.w, 0.0f);
    ((float4*)out)[idx] = y;
}

// ---------------------------------------------------------------------------
extern "C" void kernel_launch(void* const* d_in, const int* in_sizes, int n_in,
                              void* d_out, int out_size) {
    const float* x     = (const float*)d_in[0];
    const void*  eidx  = d_in[1];               // int64 or int32, detected on device
    const float* W     = (const float*)d_in[2];
    const float* bias  = (const float*)d_in[3];
    const float* gamma = (const float*)d_in[4];
    const float* beta  = (const float*)d_in[5];
    float* out = (float*)d_out;

    detect_kernel<<<1, 32>>>((const unsigned int*)eidx);
    zero_kernel<<<(N_NODES + 255) / 256, 256>>>();
    deg_kernel<<<(N_EDGES + 255) / 256, 256>>>(eidx);
    dinv_kernel<<<(N_NODES + 255) / 256, 256>>>();

    dim3 ggrid(2, (N_NODES + 127) / 128);       // BN=128 -> 2 n-tiles
    gemm_tf32_kernel<<<ggrid, 256>>>(x, W, bias, out);

    // one warp per edge: 8 warps/block -> 100000 blocks
    scatter_kernel<<<(N_EDGES + 7) / 8, 256>>>(eidx, out);

    stats_kernel<<<(N_NODES + 255) / 256, 256>>>(out);

    int nvec = N_NODES * (D / 4);
    finalize_kernel<<<(nvec + 255) / 256, 256>>>(gamma, beta, out);
}

// round 5
// speedup vs baseline: 2.2259x; 1.5086x over previous
#include <cuda_runtime.h>
#include <cstdint>

constexpr int N_NODES = 50000;
constexpr int N_EDGES = 800000;
constexpr int D       = 256;
constexpr float BN_EPS = 1e-5f;
constexpr int NBLK = (N_NODES + 255) / 256;   // 196 scan blocks

// -------- device scratch --------
__device__ float g_h[(size_t)N_NODES * D];    // h = x @ W^T
__device__ float g_dinv[N_NODES];
__device__ int   g_cnt[N_NODES];
__device__ int   g_off[N_NODES];
__device__ int   g_cur[N_NODES];
__device__ int   g_bsum[256];
__device__ int   g_src[N_EDGES];
__device__ float g_sum[D];
__device__ float g_sumsq[D];
__device__ int   g_is64;

__device__ __forceinline__ int edge_idx(const void* e, long long pos, int is64) {
    if (is64) return (int)((const long long*)e)[pos];
    return ((const int*)e)[pos];
}

__device__ __forceinline__ uint32_t f2tf32(float x) {
    uint32_t r;
    asm("cvt.rna.tf32.f32 %0, %1;" : "=r"(r) : "f"(x));
    return r;
}

// -------- 0: detect edge_index width (int64 vs int32) --------
__global__ void detect_kernel(const unsigned int* e) {
    int lane = threadIdx.x;
    unsigned v = e[2 * lane + 1] | e[2 * (lane + 32) + 1];
    unsigned any = __ballot_sync(0xffffffffu, v != 0u);
    if (lane == 0) g_is64 = (any == 0u) ? 1 : 0;
}

// -------- 1: zero --------
__global__ void zero_kernel() {
    int i = blockIdx.x * blockDim.x + threadIdx.x;
    if (i < N_NODES) g_cnt[i] = 0;
    if (i < D) { g_sum[i] = 0.0f; g_sumsq[i] = 0.0f; }
}

// -------- 2: in-degree counts over col --------
__global__ void count_kernel(const void* eidx) {
    int e = blockIdx.x * blockDim.x + threadIdx.x;
    if (e >= N_EDGES) return;
    int c = edge_idx(eidx, (long long)N_EDGES + e, g_is64);
    atomicAdd(&g_cnt[c], 1);
}

// -------- 3: block-wise exclusive scan of counts --------
__global__ void scan1_kernel() {
    __shared__ int s[256];
    int t = threadIdx.x;
    int i = blockIdx.x * 256 + t;
    int v = (i < N_NODES) ? g_cnt[i] : 0;
    s[t] = v;
    __syncthreads();
#pragma unroll
    for (int off = 1; off < 256; off <<= 1) {
        int u = (t >= off) ? s[t - off] : 0;
        __syncthreads();
        s[t] += u;
        __syncthreads();
    }
    if (i < N_NODES) g_off[i] = s[t] - v;      // exclusive within block
    if (t == 255) g_bsum[blockIdx.x] = s[255]; // block total
}

__global__ void scan2_kernel() {
    __shared__ int s[256];
    int t = threadIdx.x;
    int v = (t < NBLK) ? g_bsum[t] : 0;
    s[t] = v;
    __syncthreads();
#pragma unroll
    for (int off = 1; off < 256; off <<= 1) {
        int u = (t >= off) ? s[t - off] : 0;
        __syncthreads();
        s[t] += u;
        __syncthreads();
    }
    g_bsum[t] = s[t] - v;                      // exclusive block offsets
}

// -------- 4: finalize offsets, init cursor, compute dinv --------
__global__ void scan3_kernel() {
    int i = blockIdx.x * blockDim.x + threadIdx.x;
    if (i >= N_NODES) return;
    int o = g_off[i] + g_bsum[i >> 8];
    g_off[i] = o;
    g_cur[i] = o;
    g_dinv[i] = rsqrtf((float)g_cnt[i] + 1.0f);  // +1 self loop
}

// -------- 5: bin edges by target node --------
__global__ void fill_kernel(const void* eidx) {
    int e = blockIdx.x * blockDim.x + threadIdx.x;
    if (e >= N_EDGES) return;
    int is64 = g_is64;
    int r = edge_idx(eidx, e, is64);
    int c = edge_idx(eidx, (long long)N_EDGES + e, is64);
    int pos = atomicAdd(&g_cur[c], 1);
    g_src[pos] = r;
}

// -------- 6: tf32 tensor-core GEMM (writes g_h only) --------
constexpr int BK = 32;
constexpr int KS = BK + 4;

__global__ void __launch_bounds__(256, 2) gemm_tf32_kernel(const float* __restrict__ X,
                                                           const float* __restrict__ W) {
    __shared__ uint32_t As[128][KS];
    __shared__ uint32_t Bs[128][KS];

    const int tid  = threadIdx.x;
    const int lane = tid & 31;
    const int wid  = tid >> 5;
    const int grp  = lane >> 2;
    const int tq   = lane & 3;
    const int warp_m = wid & 1;
    const int warp_n = wid >> 1;
    const int wm0 = warp_m * 64;
    const int wn0 = warp_n * 32;
    const int m0 = blockIdx.y * 128;
    const int n0 = blockIdx.x * 128;

    const int ldrow = tid >> 3;
    const int ldk   = (tid & 7) * 4;

    float acc[4][4][4];
#pragma unroll
    for (int mi = 0; mi < 4; ++mi)
#pragma unroll
        for (int ni = 0; ni < 4; ++ni)
#pragma unroll
            for (int j = 0; j < 4; ++j) acc[mi][ni][j] = 0.0f;

    for (int k0 = 0; k0 < 256; k0 += BK) {
#pragma unroll
        for (int it = 0; it < 4; ++it) {
            int row = ldrow + it * 32;
            int gm = m0 + row;
            float4 a = make_float4(0.f, 0.f, 0.f, 0.f);
            if (gm < N_NODES)
                a = *(const float4*)(X + (size_t)gm * D + k0 + ldk);
            uint4 at;
            at.x = f2tf32(a.x); at.y = f2tf32(a.y);
            at.z = f2tf32(a.z); at.w = f2tf32(a.w);
            *(uint4*)(&As[row][ldk]) = at;
            int gn = n0 + row;
            float4 b = *(const float4*)(W + (size_t)gn * D + k0 + ldk);
            uint4 bt;
            bt.x = f2tf32(b.x); bt.y = f2tf32(b.y);
            bt.z = f2tf32(b.z); bt.w = f2tf32(b.w);
            *(uint4*)(&Bs[row][ldk]) = bt;
        }
        __syncthreads();

#pragma unroll
        for (int kk = 0; kk < 4; ++kk) {
            const int kb = kk * 8;
            uint32_t aR[4][4];
#pragma unroll
            for (int mi = 0; mi < 4; ++mi) {
                int mb = wm0 + mi * 16;
                aR[mi][0] = As[mb + grp][kb + tq];
                aR[mi][1] = As[mb + grp + 8][kb + tq];
                aR[mi][2] = As[mb + grp][kb + tq + 4];
                aR[mi][3] = As[mb + grp + 8][kb + tq + 4];
            }
            uint32_t bR[4][2];
#pragma unroll
            for (int ni = 0; ni < 4; ++ni) {
                int nb = wn0 + ni * 8;
                bR[ni][0] = Bs[nb + grp][kb + tq];
                bR[ni][1] = Bs[nb + grp][kb + tq + 4];
            }
#pragma unroll
            for (int mi = 0; mi < 4; ++mi)
#pragma unroll
                for (int ni = 0; ni < 4; ++ni) {
                    asm volatile(
                        "mma.sync.aligned.m16n8k8.row.col.f32.tf32.tf32.f32 "
                        "{%0,%1,%2,%3}, {%4,%5,%6,%7}, {%8,%9}, {%0,%1,%2,%3};\n"
                        : "+f"(acc[mi][ni][0]), "+f"(acc[mi][ni][1]),
                          "+f"(acc[mi][ni][2]), "+f"(acc[mi][ni][3])
                        : "r"(aR[mi][0]), "r"(aR[mi][1]), "r"(aR[mi][2]), "r"(aR[mi][3]),
                          "r"(bR[ni][0]), "r"(bR[ni][1]));
                }
        }
        __syncthreads();
    }

#pragma unroll
    for (int mi = 0; mi < 4; ++mi) {
#pragma unroll
        for (int half = 0; half < 2; ++half) {
            int r = m0 + wm0 + mi * 16 + grp + half * 8;
            if (r >= N_NODES) continue;
            float* hrow = g_h + (size_t)r * D;
#pragma unroll
            for (int ni = 0; ni < 4; ++ni) {
                int c = n0 + wn0 + ni * 8 + tq * 2;
                *(float2*)(hrow + c) =
                    make_float2(acc[mi][ni][half * 2 + 0], acc[mi][ni][half * 2 + 1]);
            }
        }
    }
}

// -------- 7: gather-aggregate (CSR), fused self-loop + bias ----------------
// 64 threads per node (float4/thread); 4 nodes per 256-thread block.
__global__ void __launch_bounds__(256) gather_kernel(const float* __restrict__ bias,
                                                     float* __restrict__ out) {
    int node = blockIdx.x * 4 + (threadIdx.x >> 6);
    int t = threadIdx.x & 63;
    if (node >= N_NODES) return;

    const int* __restrict__ src = g_src;
    const float* __restrict__ dinv = g_dinv;
    int o0 = g_off[node];
    int o1 = o0 + g_cnt[node];

    const float4* __restrict__ H = (const float4*)g_h;
    float4 acc = make_float4(0.f, 0.f, 0.f, 0.f);

    int e = o0;
    for (; e + 2 <= o1; e += 2) {
        int s0 = src[e];
        int s1 = src[e + 1];
        float d0 = dinv[s0];
        float d1 = dinv[s1];
        float4 h0 = H[(size_t)s0 * 64 + t];
        float4 h1 = H[(size_t)s1 * 64 + t];
        acc.x = fmaf(h0.x, d0, acc.x); acc.y = fmaf(h0.y, d0, acc.y);
        acc.z = fmaf(h0.z, d0, acc.z); acc.w = fmaf(h0.w, d0, acc.w);
        acc.x = fmaf(h1.x, d1, acc.x); acc.y = fmaf(h1.y, d1, acc.y);
        acc.z = fmaf(h1.z, d1, acc.z); acc.w = fmaf(h1.w, d1, acc.w);
    }
    if (e < o1) {
        int s0 = src[e];
        float d0 = dinv[s0];
        float4 h0 = H[(size_t)s0 * 64 + t];
        acc.x = fmaf(h0.x, d0, acc.x); acc.y = fmaf(h0.y, d0, acc.y);
        acc.z = fmaf(h0.z, d0, acc.z); acc.w = fmaf(h0.w, d0, acc.w);
    }

    float dn = dinv[node];
    float4 hn = H[(size_t)node * 64 + t];
    // self loop: + h[n]*dn ; then everything * dn ; + bias
    acc.x = fmaf(hn.x, dn, acc.x); acc.y = fmaf(hn.y, dn, acc.y);
    acc.z = fmaf(hn.z, dn, acc.z); acc.w = fmaf(hn.w, dn, acc.w);
    float4 b4 = ((const float4*)bias)[t];
    float4 v;
    v.x = fmaf(acc.x, dn, b4.x);
    v.y = fmaf(acc.y, dn, b4.y);
    v.z = fmaf(acc.z, dn, b4.z);
    v.w = fmaf(acc.w, dn, b4.w);
    ((float4*)out)[(size_t)node * 64 + t] = v;
}

// -------- 8: per-feature sum / sumsq --------
__global__ void __launch_bounds__(256) stats_kernel(const float* __restrict__ out) {
    const int d = threadIdx.x;
    const int r0 = blockIdx.x * 256;
    const int r1 = min(r0 + 256, N_NODES);
    float s = 0.0f, sq = 0.0f;
    for (int r = r0; r < r1; ++r) {
        float v = out[(size_t)r * D + d];
        s += v;
        sq += v * v;
    }
    atomicAdd(&g_sum[d], s);
    atomicAdd(&g_sumsq[d], sq);
}

// -------- 9: BatchNorm + ReLU in place --------
__global__ void finalize_kernel(const float* __restrict__ gamma,
                                const float* __restrict__ beta,
                                float* __restrict__ out) {
    int idx = blockIdx.x * blockDim.x + threadIdx.x;
    if (idx >= N_NODES * (D / 4)) return;
    int j4 = idx & 63;
    const float invN = 1.0f / (float)N_NODES;
    float4 s4  = ((const float4*)g_sum)[j4];
    float4 q4  = ((const float4*)g_sumsq)[j4];
    float4 g4  = ((const float4*)gamma)[j4];
    float4 b4  = ((const float4*)beta)[j4];
    float4 v = ((const float4*)out)[idx];

    float m, var, k;
    float4 y;
    m = s4.x * invN; var = q4.x * invN - m * m; k = g4.x * rsqrtf(var + BN_EPS);
    y.x = fmaxf((v.x - m) * k + b4.x, 0.0f);
    m = s4.y * invN; var = q4.y * invN - m * m; k = g4.y * rsqrtf(var + BN_EPS);
    y.y = fmaxf((v.y - m) * k + b4.y, 0.0f);
    m = s4.z * invN; var = q4.z * invN - m * m; k = g4.z * rsqrtf(var + BN_EPS);
    y.z = fmaxf((v.z - m) * k + b4.z, 0.0f);
    m = s4.w * invN; var = q4.w * invN - m * m; k = g4.w * rsqrtf(var + BN_EPS);
    y.w = fmaxf((v.w - m) * k + b4.w, 0.0f);
    ((float4*)out)[idx] = y;
}

// ---------------------------------------------------------------------------
extern "C" void kernel_launch(void* const* d_in, const int* in_sizes, int n_in,
                              void* d_out, int out_size) {
    const float* x     = (const float*)d_in[0];
    const void*  eidx  = d_in[1];
    const float* W     = (const float*)d_in[2];
    const float* bias  = (const float*)d_in[3];
    const float* gamma = (const float*)d_in[4];
    const float* beta  = (const float*)d_in[5];
    float* out = (float*)d_out;

    detect_kernel<<<1, 32>>>((const unsigned int*)eidx);
    zero_kernel<<<NBLK, 256>>>();
    count_kernel<<<(N_EDGES + 255) / 256, 256>>>(eidx);
    scan1_kernel<<<NBLK, 256>>>();
    scan2_kernel<<<1, 256>>>();
    scan3_kernel<<<NBLK, 256>>>();
    fill_kernel<<<(N_EDGES + 255) / 256, 256>>>(eidx);

    dim3 ggrid(2, (N_NODES + 127) / 128);
    gemm_tf32_kernel<<<ggrid, 256>>>(x, W);

    gather_kernel<<<(N_NODES + 3) / 4, 256>>>(bias, out);

    stats_kernel<<<NBLK, 256>>>(out);

    int nvec = N_NODES * (D / 4);
    finalize_kernel<<<(nvec + 255) / 256, 256>>>(gamma, beta, out);
}